// round 14
// baseline (speedup 1.0000x reference)
#include <cuda_runtime.h>
#include <cuda_fp16.h>
#include <cstdint>

// Problem constants
#define NN 8192
#define DD 128
static constexpr float MARGIN = 1.0f;

// Tiling (R4/R12 core, unchanged)
static constexpr int BM = 128, BN = 128, BK = 64;
static constexpr int NCH = DD / BK;           // 2 chunks
static constexpr int THREADS = 256;           // 8 warps: 2 (m) x 4 (n)
static constexpr int MAXP = 1 << 20;

// ---------------------------------------------------------------------------
// Device globals
// ---------------------------------------------------------------------------
__device__ float g_V[NN];
__device__ int   g_pair_cnt;
__device__ int   g_done_blocks;
__device__ int   g_pi[MAXP];
__device__ int   g_pj[MAXP];
__device__ float g_ps[MAXP];
__device__ __align__(16) __half g_Ah[NN * DD];
__device__ __align__(16) __half g_Bh[NN * DD];

// ---------------------------------------------------------------------------
// PTX helpers
// ---------------------------------------------------------------------------
__device__ __forceinline__ void ldsm_x4(uint32_t& r0, uint32_t& r1, uint32_t& r2, uint32_t& r3,
                                        uint32_t saddr) {
    asm volatile("ldmatrix.sync.aligned.m8n8.x4.shared.b16 {%0,%1,%2,%3}, [%4];"
                 : "=r"(r0), "=r"(r1), "=r"(r2), "=r"(r3) : "r"(saddr));
}
__device__ __forceinline__ void mma_f16(float* d,
                                        uint32_t a0, uint32_t a1, uint32_t a2, uint32_t a3,
                                        uint32_t b0, uint32_t b1) {
    asm volatile(
        "mma.sync.aligned.m16n8k16.row.col.f32.f16.f16.f32 "
        "{%0,%1,%2,%3}, {%4,%5,%6,%7}, {%8,%9}, {%0,%1,%2,%3};"
        : "+f"(d[0]), "+f"(d[1]), "+f"(d[2]), "+f"(d[3])
        : "r"(a0), "r"(a1), "r"(a2), "r"(a3), "r"(b0), "r"(b1));
}
__device__ __forceinline__ uint32_t h2u(__half2 h) {
    return *reinterpret_cast<uint32_t*>(&h);
}

// ---------------------------------------------------------------------------
// Kernel 0: f32 -> f16 conversion + accumulator zeroing (R12 form)
// ---------------------------------------------------------------------------
__global__ void k_convert(const float* __restrict__ A, const float* __restrict__ B) {
    int t = blockIdx.x * blockDim.x + threadIdx.x;     // 0 .. NN*DD/4-1
    float4 va = ((const float4*)A)[t];
    float4 vb = ((const float4*)B)[t];
    uint2 ua = make_uint2(h2u(__floats2half2_rn(va.x, va.y)),
                          h2u(__floats2half2_rn(va.z, va.w)));
    uint2 ub = make_uint2(h2u(__floats2half2_rn(vb.x, vb.y)),
                          h2u(__floats2half2_rn(vb.z, vb.w)));
    ((uint2*)g_Ah)[t] = ua;
    ((uint2*)g_Bh)[t] = ub;
    if (t < NN) g_V[t] = 0.0f;
    if (t == 0) { g_pair_cnt = 0; g_done_blocks = 0; }
}

// ---------------------------------------------------------------------------
// Kernel 1: fp16 mma.sync GEMM (f32 accum) — R12 core, plus:
// the LAST-finishing CTA (done-block counter) runs the pair/hinge pass and
// writes the final scalar. No separate k_pairs launch.
// ---------------------------------------------------------------------------
__global__ __launch_bounds__(THREADS, 2)
void k_gemm(const int* __restrict__ labels, float* __restrict__ out) {
    __shared__ __align__(16) __half As[BM * BK];   // 16 KB
    __shared__ __align__(16) __half Bs[BN * BK];   // 16 KB
    __shared__ float sV[BM];
    __shared__ int   sLi[BM];
    __shared__ int   sLj[BN];
    __shared__ int   s_last;

    const int tid  = threadIdx.x;
    const int wid  = tid >> 5;
    const int lane = tid & 31;
    const int g    = lane >> 2;       // 0..7
    const int l4   = lane & 3;        // 0..3
    const int wm   = wid >> 2;        // 0..1
    const int wn   = wid & 3;         // 0..3
    const int bi   = blockIdx.y * BM;
    const int bj   = blockIdx.x * BN;

    if (tid < BM) { sV[tid] = 0.0f; sLi[tid] = labels[bi + tid]; }
    else if (tid < BM + BN) { sLj[tid - BM] = labels[bj + (tid - BM)]; }

    const uint32_t as_base = (uint32_t)__cvta_generic_to_shared(As);
    const uint32_t bs_base = (uint32_t)__cvta_generic_to_shared(Bs);

    // ldmatrix lane-address precompute
    const int q  = lane >> 3;
    const int rr = lane & 7;
    uint32_t a_rowbase[4];
    int      a_sw[4];
    const int a_cq = q >> 1;
#pragma unroll
    for (int mi = 0; mi < 4; ++mi) {
        int row = wm * 64 + mi * 16 + (q & 1) * 8 + rr;
        a_rowbase[mi] = as_base + row * (BK * 2);
        a_sw[mi] = row & 7;
    }
    uint32_t b_rowbase[2];
    int      b_sw[2];
    const int b_cq = q & 1;
#pragma unroll
    for (int p = 0; p < 2; ++p) {
        int n = wn * 32 + p * 16 + (q >> 1) * 8 + rr;
        b_rowbase[p] = bs_base + n * (BK * 2);
        b_sw[p] = n & 7;
    }

    float acc[4][4][4];
#pragma unroll
    for (int mi = 0; mi < 4; ++mi)
#pragma unroll
        for (int ni = 0; ni < 4; ++ni)
#pragma unroll
            for (int e = 0; e < 4; ++e) acc[mi][ni][e] = 0.0f;

    for (int c = 0; c < NCH; ++c) {
        const int k0 = c * BK;
        if (c > 0) __syncthreads();

#pragma unroll
        for (int t = 0; t < 4; ++t) {
            int idx = tid + t * THREADS;           // 0..1023
            int row = idx >> 3;                    // 0..127
            int cc  = idx & 7;                     // 16B chunk 0..7
            int sw  = cc ^ (row & 7);
            *(uint4*)&As[row * BK + sw * 8] =
                *(const uint4*)&g_Ah[(size_t)(bi + row) * DD + k0 + cc * 8];
            *(uint4*)&Bs[row * BK + sw * 8] =
                *(const uint4*)&g_Bh[(size_t)(bj + row) * DD + k0 + cc * 8];
        }
        __syncthreads();

#pragma unroll
        for (int kk = 0; kk < BK / 16; ++kk) {     // 4 k16 steps
            const int cb = kk * 2;
            uint32_t af[4][4];
#pragma unroll
            for (int mi = 0; mi < 4; ++mi)
                ldsm_x4(af[mi][0], af[mi][1], af[mi][2], af[mi][3],
                        a_rowbase[mi] + (((cb + a_cq) ^ a_sw[mi]) << 4));
            uint32_t bf[2][4];
#pragma unroll
            for (int p = 0; p < 2; ++p)
                ldsm_x4(bf[p][0], bf[p][1], bf[p][2], bf[p][3],
                        b_rowbase[p] + (((cb + b_cq) ^ b_sw[p]) << 4));
#pragma unroll
            for (int mi = 0; mi < 4; ++mi) {
#pragma unroll
                for (int p = 0; p < 2; ++p) {
                    mma_f16(acc[mi][2 * p + 0], af[mi][0], af[mi][1], af[mi][2], af[mi][3],
                            bf[p][0], bf[p][1]);
                    mma_f16(acc[mi][2 * p + 1], af[mi][0], af[mi][1], af[mi][2], af[mi][3],
                            bf[p][2], bf[p][3]);
                }
            }
        }
    }
    __syncthreads();

    // ---------------- Epilogue (R12) ----------------
#pragma unroll
    for (int mi = 0; mi < 4; ++mi) {
        const int row0 = wm * 64 + mi * 16 + g;
        const int row1 = row0 + 8;
        const int li0 = sLi[row0], li1 = sLi[row1];
        float v0 = 0.0f, v1 = 0.0f;
#pragma unroll
        for (int ni = 0; ni < 4; ++ni) {
            const int colb = wn * 32 + ni * 8 + 2 * l4;
            const int ljA = sLj[colb], ljB = sLj[colb + 1];
#pragma unroll
            for (int e = 0; e < 4; ++e) {
                const float s = acc[mi][ni][e];
                const int row = (e & 2) ? row1 : row0;
                const int li  = (e & 2) ? li1 : li0;
                const int col = colb + (e & 1);
                const int lj  = (e & 1) ? ljB : ljA;
                if (li != lj) {
                    float ev = __expf(MARGIN + s);
                    if (e & 2) v1 += ev; else v0 += ev;
                } else {
                    int gi = bi + row, gj = bj + col;
                    if (gi != gj) {
                        int idx = atomicAdd(&g_pair_cnt, 1);
                        if (idx < MAXP) { g_pi[idx] = gi; g_pj[idx] = gj; g_ps[idx] = s; }
                    }
                }
            }
        }
        v0 += __shfl_xor_sync(0xffffffffu, v0, 1);
        v0 += __shfl_xor_sync(0xffffffffu, v0, 2);
        v1 += __shfl_xor_sync(0xffffffffu, v1, 1);
        v1 += __shfl_xor_sync(0xffffffffu, v1, 2);
        if (l4 == 0) {
            atomicAdd(&sV[row0], v0);
            atomicAdd(&sV[row1], v1);
        }
    }
    __syncthreads();
    if (tid < BM) atomicAdd(&g_V[bi + tid], sV[tid]);

    // ---------------- Last-CTA pair/hinge pass ----------------
    __threadfence();            // make this CTA's g_V / pair-list writes visible
    __syncthreads();            // all threads' work (incl. V atomics) done
    if (tid == 0) s_last = atomicAdd(&g_done_blocks, 1);
    __syncthreads();
    if (s_last != gridDim.x * gridDim.y - 1) return;

    // This is the last CTA: every other CTA's writes are visible (their
    // atomicAdd to g_done_blocks followed a __threadfence).
    int n = g_pair_cnt;
    if (n > MAXP) n = MAXP;
    float local = 0.0f;
    for (int p = tid; p < n; p += THREADS) {
        float v = g_V[g_pi[p]] + g_V[g_pj[p]];
        float h = fmaxf(logf(v) - g_ps[p], 0.0f);
        local += h * h;
    }
    local += __shfl_xor_sync(0xffffffffu, local, 16);
    local += __shfl_xor_sync(0xffffffffu, local, 8);
    local += __shfl_xor_sync(0xffffffffu, local, 4);
    local += __shfl_xor_sync(0xffffffffu, local, 2);
    local += __shfl_xor_sync(0xffffffffu, local, 1);

    __shared__ float wsum[8];
    if (lane == 0) wsum[wid] = local;
    __syncthreads();
    if (tid == 0) {
        float s = 0.0f;
#pragma unroll
        for (int i = 0; i < THREADS / 32; ++i) s += wsum[i];
        out[0] = s / (2.0f * (float)g_pair_cnt);
    }
}

// ---------------------------------------------------------------------------
extern "C" void kernel_launch(void* const* d_in, const int* in_sizes, int n_in,
                              void* d_out, int out_size) {
    const float* a      = (const float*)d_in[0];
    const float* b      = (const float*)d_in[1];
    const int*   labels = (const int*)d_in[2];
    float*       out    = (float*)d_out;

    k_convert<<<(NN * DD / 4) / 256, 256>>>(a, b);

    dim3 grid(NN / BN, NN / BM);   // 64 x 64
    k_gemm<<<grid, THREADS>>>(labels, out);
}

// round 15
// speedup vs baseline: 1.5208x; 1.5208x over previous
#include <cuda_runtime.h>
#include <cuda_fp16.h>
#include <cstdint>

// Problem constants
#define NN 8192
#define DD 128
static constexpr float MARGIN = 1.0f;

// Tiling: 64x128 CTA tile for higher occupancy (acc = 32 regs/thread)
static constexpr int BM = 64, BN = 128, BK = 64;
static constexpr int NCH = DD / BK;           // 2 chunks
static constexpr int THREADS = 256;           // 8 warps: 2 (m) x 4 (n), 32x32 warp tiles
static constexpr int MAXP = 1 << 20;
static constexpr int PAIR_BLOCKS = 64;

// ---------------------------------------------------------------------------
// Device globals
// ---------------------------------------------------------------------------
__device__ float g_V[NN];
__device__ float g_loss_sum;
__device__ int   g_pair_cnt;
__device__ int   g_done_blocks;
__device__ int   g_pi[MAXP];
__device__ int   g_pj[MAXP];
__device__ float g_ps[MAXP];
__device__ __align__(16) __half g_Ah[NN * DD];
__device__ __align__(16) __half g_Bh[NN * DD];

// ---------------------------------------------------------------------------
// PTX helpers
// ---------------------------------------------------------------------------
__device__ __forceinline__ void ldsm_x4(uint32_t& r0, uint32_t& r1, uint32_t& r2, uint32_t& r3,
                                        uint32_t saddr) {
    asm volatile("ldmatrix.sync.aligned.m8n8.x4.shared.b16 {%0,%1,%2,%3}, [%4];"
                 : "=r"(r0), "=r"(r1), "=r"(r2), "=r"(r3) : "r"(saddr));
}
__device__ __forceinline__ void mma_f16(float* d,
                                        uint32_t a0, uint32_t a1, uint32_t a2, uint32_t a3,
                                        uint32_t b0, uint32_t b1) {
    asm volatile(
        "mma.sync.aligned.m16n8k16.row.col.f32.f16.f16.f32 "
        "{%0,%1,%2,%3}, {%4,%5,%6,%7}, {%8,%9}, {%0,%1,%2,%3};"
        : "+f"(d[0]), "+f"(d[1]), "+f"(d[2]), "+f"(d[3])
        : "r"(a0), "r"(a1), "r"(a2), "r"(a3), "r"(b0), "r"(b1));
}
__device__ __forceinline__ uint32_t h2u(__half2 h) {
    return *reinterpret_cast<uint32_t*>(&h);
}

// ---------------------------------------------------------------------------
// Kernel 0: f32 -> f16 conversion + accumulator zeroing (R12 form)
// ---------------------------------------------------------------------------
__global__ void k_convert(const float* __restrict__ A, const float* __restrict__ B) {
    int t = blockIdx.x * blockDim.x + threadIdx.x;     // 0 .. NN*DD/4-1
    float4 va = ((const float4*)A)[t];
    float4 vb = ((const float4*)B)[t];
    uint2 ua = make_uint2(h2u(__floats2half2_rn(va.x, va.y)),
                          h2u(__floats2half2_rn(va.z, va.w)));
    uint2 ub = make_uint2(h2u(__floats2half2_rn(vb.x, vb.y)),
                          h2u(__floats2half2_rn(vb.z, vb.w)));
    ((uint2*)g_Ah)[t] = ua;
    ((uint2*)g_Bh)[t] = ub;
    if (t < NN) g_V[t] = 0.0f;
    if (t == 0) { g_loss_sum = 0.0f; g_pair_cnt = 0; g_done_blocks = 0; }
}

// ---------------------------------------------------------------------------
// Kernel 1: fp16 mma.sync GEMM (f32 accum), 64x128 tile, occupancy 3.
// Fused epilogue: V[i] += sum_{labels differ} exp(MARGIN + S_ij);
// capture positive pairs (i, j, S_ij).
// ---------------------------------------------------------------------------
__global__ __launch_bounds__(THREADS, 3)
void k_gemm(const int* __restrict__ labels) {
    __shared__ __align__(16) __half As[BM * BK];   // 8 KB
    __shared__ __align__(16) __half Bs[BN * BK];   // 16 KB
    __shared__ float sV[BM];
    __shared__ int   sLi[BM];
    __shared__ int   sLj[BN];

    const int tid  = threadIdx.x;
    const int wid  = tid >> 5;
    const int lane = tid & 31;
    const int g    = lane >> 2;       // 0..7
    const int l4   = lane & 3;        // 0..3
    const int wm   = wid >> 2;        // 0..1 -> m offset 32*wm
    const int wn   = wid & 3;         // 0..3 -> n offset 32*wn
    const int bi   = blockIdx.y * BM;
    const int bj   = blockIdx.x * BN;

    if (tid < BM) { sV[tid] = 0.0f; sLi[tid] = labels[bi + tid]; }
    else if (tid < BM + BN) { sLj[tid - BM] = labels[bj + (tid - BM)]; }

    const uint32_t as_base = (uint32_t)__cvta_generic_to_shared(As);
    const uint32_t bs_base = (uint32_t)__cvta_generic_to_shared(Bs);

    // ldmatrix lane-address precompute
    const int q  = lane >> 3;
    const int rr = lane & 7;
    uint32_t a_rowbase[2];
    int      a_sw[2];
    const int a_cq = q >> 1;
#pragma unroll
    for (int mi = 0; mi < 2; ++mi) {
        int row = wm * 32 + mi * 16 + (q & 1) * 8 + rr;
        a_rowbase[mi] = as_base + row * (BK * 2);
        a_sw[mi] = row & 7;
    }
    uint32_t b_rowbase[2];
    int      b_sw[2];
    const int b_cq = q & 1;
#pragma unroll
    for (int p = 0; p < 2; ++p) {
        int n = wn * 32 + p * 16 + (q >> 1) * 8 + rr;
        b_rowbase[p] = bs_base + n * (BK * 2);
        b_sw[p] = n & 7;
    }

    float acc[2][4][4];
#pragma unroll
    for (int mi = 0; mi < 2; ++mi)
#pragma unroll
        for (int ni = 0; ni < 4; ++ni)
#pragma unroll
            for (int e = 0; e < 4; ++e) acc[mi][ni][e] = 0.0f;

    for (int c = 0; c < NCH; ++c) {
        const int k0 = c * BK;
        if (c > 0) __syncthreads();

        // Load tiles: A = 512 uint4, B = 1024 uint4 -> 6 per thread
#pragma unroll
        for (int t = 0; t < 6; ++t) {
            int idx = tid + t * THREADS;           // 0..1535
            if (idx < 512) {
                int row = idx >> 3;                // 0..63
                int cc  = idx & 7;
                int sw  = cc ^ (row & 7);
                *(uint4*)&As[row * BK + sw * 8] =
                    *(const uint4*)&g_Ah[(size_t)(bi + row) * DD + k0 + cc * 8];
            } else {
                int j   = idx - 512;               // 0..1023
                int row = j >> 3;                  // 0..127
                int cc  = j & 7;
                int sw  = cc ^ (row & 7);
                *(uint4*)&Bs[row * BK + sw * 8] =
                    *(const uint4*)&g_Bh[(size_t)(bj + row) * DD + k0 + cc * 8];
            }
        }
        __syncthreads();

#pragma unroll
        for (int kk = 0; kk < BK / 16; ++kk) {     // 4 k16 steps
            const int cb = kk * 2;
            uint32_t af[2][4];
#pragma unroll
            for (int mi = 0; mi < 2; ++mi)
                ldsm_x4(af[mi][0], af[mi][1], af[mi][2], af[mi][3],
                        a_rowbase[mi] + (((cb + a_cq) ^ a_sw[mi]) << 4));
            uint32_t bf[2][4];
#pragma unroll
            for (int p = 0; p < 2; ++p)
                ldsm_x4(bf[p][0], bf[p][1], bf[p][2], bf[p][3],
                        b_rowbase[p] + (((cb + b_cq) ^ b_sw[p]) << 4));
#pragma unroll
            for (int mi = 0; mi < 2; ++mi) {
#pragma unroll
                for (int p = 0; p < 2; ++p) {
                    mma_f16(acc[mi][2 * p + 0], af[mi][0], af[mi][1], af[mi][2], af[mi][3],
                            bf[p][0], bf[p][1]);
                    mma_f16(acc[mi][2 * p + 1], af[mi][0], af[mi][1], af[mi][2], af[mi][3],
                            bf[p][2], bf[p][3]);
                }
            }
        }
    }
    __syncthreads();

    // ---------------- Epilogue ----------------
#pragma unroll
    for (int mi = 0; mi < 2; ++mi) {
        const int row0 = wm * 32 + mi * 16 + g;
        const int row1 = row0 + 8;
        const int li0 = sLi[row0], li1 = sLi[row1];
        float v0 = 0.0f, v1 = 0.0f;
#pragma unroll
        for (int ni = 0; ni < 4; ++ni) {
            const int colb = wn * 32 + ni * 8 + 2 * l4;
            const int ljA = sLj[colb], ljB = sLj[colb + 1];
#pragma unroll
            for (int e = 0; e < 4; ++e) {
                const float s = acc[mi][ni][e];
                const int row = (e & 2) ? row1 : row0;
                const int li  = (e & 2) ? li1 : li0;
                const int col = colb + (e & 1);
                const int lj  = (e & 1) ? ljB : ljA;
                if (li != lj) {
                    float ev = __expf(MARGIN + s);
                    if (e & 2) v1 += ev; else v0 += ev;
                } else {
                    int gi = bi + row, gj = bj + col;
                    if (gi != gj) {
                        int idx = atomicAdd(&g_pair_cnt, 1);
                        if (idx < MAXP) { g_pi[idx] = gi; g_pj[idx] = gj; g_ps[idx] = s; }
                    }
                }
            }
        }
        v0 += __shfl_xor_sync(0xffffffffu, v0, 1);
        v0 += __shfl_xor_sync(0xffffffffu, v0, 2);
        v1 += __shfl_xor_sync(0xffffffffu, v1, 1);
        v1 += __shfl_xor_sync(0xffffffffu, v1, 2);
        if (l4 == 0) {
            atomicAdd(&sV[row0], v0);
            atomicAdd(&sV[row1], v1);
        }
    }
    __syncthreads();
    if (tid < BM) atomicAdd(&g_V[bi + tid], sV[tid]);
}

// ---------------------------------------------------------------------------
// Kernel 2: hinge over the positive-pair list + final scalar (merged)
// ---------------------------------------------------------------------------
__global__ void k_pairs(float* __restrict__ out) {
    int n = g_pair_cnt;
    if (n > MAXP) n = MAXP;
    float local = 0.0f;
    for (int p = blockIdx.x * blockDim.x + threadIdx.x; p < n;
         p += gridDim.x * blockDim.x) {
        float v = g_V[g_pi[p]] + g_V[g_pj[p]];
        float h = fmaxf(logf(v) - g_ps[p], 0.0f);
        local += h * h;
    }
    local += __shfl_xor_sync(0xffffffffu, local, 16);
    local += __shfl_xor_sync(0xffffffffu, local, 8);
    local += __shfl_xor_sync(0xffffffffu, local, 4);
    local += __shfl_xor_sync(0xffffffffu, local, 2);
    local += __shfl_xor_sync(0xffffffffu, local, 1);

    __shared__ float wsum[8];
    int lane = threadIdx.x & 31, w = threadIdx.x >> 5;
    if (lane == 0) wsum[w] = local;
    __syncthreads();
    if (threadIdx.x == 0) {
        float s = 0.0f;
        int nw = (blockDim.x + 31) >> 5;
        for (int i = 0; i < nw; ++i) s += wsum[i];
        atomicAdd(&g_loss_sum, s);
        __threadfence();
        int done = atomicAdd(&g_done_blocks, 1);
        if (done == gridDim.x - 1) {
            out[0] = g_loss_sum / (2.0f * (float)g_pair_cnt);
        }
    }
}

// ---------------------------------------------------------------------------
extern "C" void kernel_launch(void* const* d_in, const int* in_sizes, int n_in,
                              void* d_out, int out_size) {
    const float* a      = (const float*)d_in[0];
    const float* b      = (const float*)d_in[1];
    const int*   labels = (const int*)d_in[2];
    float*       out    = (float*)d_out;

    k_convert<<<(NN * DD / 4) / 256, 256>>>(a, b);

    dim3 grid(NN / BN, NN / BM);   // 64 x 128
    k_gemm<<<grid, THREADS>>>(labels);

    k_pairs<<<PAIR_BLOCKS, 256>>>(out);
}